// round 6
// baseline (speedup 1.0000x reference)
#include <cuda_runtime.h>

// SpikingCell recurrence, simplified (see R1):
//   clamp gate always-true -> dropped; spike counter unused -> dropped
//   per (b,n):  v += (refrac>=2) ? x[t-1] : 0 ; out=(v>=1); v-=out;
//               refrac = out ? 0 : refrac+1
// Pure streaming: 128MB in, 128MB out, zero reuse -> DRAM mixed R/W bound.
// R4 (depth) and R5 (float2 grain) were both neutral at ~5.6TB/s, so the
// residual 29% DRAM-idle is R/W turnaround + any request-supply micro-gaps.
// R6: float4/thread (LDG.128/STG.128, 512B/warp) halves L1 wavefronts and
// instruction count again, keeping the proven geometry: 1024 blocks
// (6.92/SM, ~1% imbalance) x 32 threads, ping-pong PF=8 float4 batches
// (~28KB/SM in flight, the proven-sufficient level).

constexpr int B = 16, T = 256, N = 8192;
constexpr int N4 = N / 4;                  // float4 lanes per row = 2048
constexpr int THREADS = 32;
constexpr int GRID = (B * N4) / THREADS;   // 1024 blocks
constexpr int PF = 8;                      // pipeline depth (float4 t-steps)
constexpr int NBATCH = T / PF;             // 32 batches -> 16 ping-pong pairs

__device__ __forceinline__ void step(const float4& d,
                                     float& v0, float& v1, float& v2, float& v3,
                                     int& r0, int& r1, int& r2, int& r3,
                                     float4& o)
{
    v0 += (r0 >= 2) ? d.x : 0.f;
    o.x = (v0 >= 1.f) ? 1.f : 0.f;
    v0 -= o.x;
    r0 = (o.x != 0.f) ? 0 : (r0 + 1);

    v1 += (r1 >= 2) ? d.y : 0.f;
    o.y = (v1 >= 1.f) ? 1.f : 0.f;
    v1 -= o.y;
    r1 = (o.y != 0.f) ? 0 : (r1 + 1);

    v2 += (r2 >= 2) ? d.z : 0.f;
    o.z = (v2 >= 1.f) ? 1.f : 0.f;
    v2 -= o.z;
    r2 = (o.z != 0.f) ? 0 : (r2 + 1);

    v3 += (r3 >= 2) ? d.w : 0.f;
    o.w = (v3 >= 1.f) ? 1.f : 0.f;
    v3 -= o.w;
    r3 = (o.w != 0.f) ? 0 : (r3 + 1);
}

__global__ __launch_bounds__(THREADS) void spiking_kernel(
    const float4* __restrict__ x, float4* __restrict__ out)
{
    int tid = blockIdx.x * THREADS + threadIdx.x;   // 0 .. B*N4-1
    int b = tid >> 11;            // / N4
    int c = tid & (N4 - 1);       // % N4
    size_t base = (size_t)b * T * N4 + c;

    const float4* __restrict__ xp = x + base;
    float4* __restrict__ op = out + base;

    float v0 = 0.f, v1 = 0.f, v2 = 0.f, v3 = 0.f;   // membrane potentials
    int   r0 = 0,   r1 = 0,   r2 = 0,   r3 = 0;     // refractory counters
    float4 d = make_float4(0.f, 0.f, 0.f, 0.f);     // dv buffer (x[t-1])

    float4 bufA[PF], bufB[PF];

    // prologue: fill A
#pragma unroll
    for (int i = 0; i < PF; i++) bufA[i] = __ldcs(xp + (size_t)i * N4);
    xp += (size_t)PF * N4;

#pragma unroll 1
    for (int pair = 0; pair < NBATCH / 2 - 1; pair++) {
        // load B, compute+store A
#pragma unroll
        for (int i = 0; i < PF; i++) bufB[i] = __ldcs(xp + (size_t)i * N4);
        xp += (size_t)PF * N4;
#pragma unroll
        for (int i = 0; i < PF; i++) {
            float4 o;
            step(d, v0, v1, v2, v3, r0, r1, r2, r3, o);
            __stcs(op, o); op += N4;
            d = bufA[i];
        }
        // load A, compute+store B
#pragma unroll
        for (int i = 0; i < PF; i++) bufA[i] = __ldcs(xp + (size_t)i * N4);
        xp += (size_t)PF * N4;
#pragma unroll
        for (int i = 0; i < PF; i++) {
            float4 o;
            step(d, v0, v1, v2, v3, r0, r1, r2, r3, o);
            __stcs(op, o); op += N4;
            d = bufB[i];
        }
    }

    // tail: load final B, compute A, then compute B
#pragma unroll
    for (int i = 0; i < PF; i++) bufB[i] = __ldcs(xp + (size_t)i * N4);
#pragma unroll
    for (int i = 0; i < PF; i++) {
        float4 o;
        step(d, v0, v1, v2, v3, r0, r1, r2, r3, o);
        __stcs(op, o); op += N4;
        d = bufA[i];
    }
#pragma unroll
    for (int i = 0; i < PF; i++) {
        float4 o;
        step(d, v0, v1, v2, v3, r0, r1, r2, r3, o);
        __stcs(op, o); op += N4;
        d = bufB[i];
    }
}

extern "C" void kernel_launch(void* const* d_in, const int* in_sizes, int n_in,
                              void* d_out, int out_size)
{
    const float4* x = (const float4*)d_in[0];
    float4* out = (float4*)d_out;
    spiking_kernel<<<GRID, THREADS>>>(x, out);
}